// round 7
// baseline (speedup 1.0000x reference)
#include <cuda_runtime.h>
#include <cuda_bf16.h>

// Problem constants
#define B_   2
#define T_   128
#define C_   527
#define DA_  1024
#define DW_  300
#define H_   1024
#define BT_  (B_ * T_)   // 256

typedef unsigned long long u64;

// ---------------- device scratch ----------------
__device__ float g_apart[2 * BT_ * H_];  // split-K partials for fc_1
__device__ float g_w[C_ * H_];           // fc_2 output [527,1024]
__device__ float g_vpart[4 * H_];        // veff partials (4 o-chunks)
__device__ float g_score0[BT_ * C_];     // partial score (h first half)
__device__ float g_score1[BT_ * C_];     // partial score (h second half)
__device__ float g_coef[BT_ * C_];       // softmax over T

__device__ __forceinline__ float tanh_fast(float x) {
    float y;
    asm("tanh.approx.f32 %0, %1;" : "=f"(y) : "f"(x));
    return y;
}
__device__ __forceinline__ void fma2(u64& d, u64 a, u64 b) {
    asm("fma.rn.f32x2 %0, %1, %2, %0;" : "+l"(d) : "l"(a), "l"(b));
}
__device__ __forceinline__ float unpk_sum(u64 v) {
    float lo, hi;
    asm("mov.b64 {%0,%1}, %2;" : "=f"(lo), "=f"(hi) : "l"(v));
    return lo + hi;
}
// acc += tanh(a*w) * v, packed over an h-pair
__device__ __forceinline__ void tvstep(u64& acc, u64 a, u64 w, u64 v) {
    u64 x;
    asm("mul.rn.f32x2 %0, %1, %2;" : "=l"(x) : "l"(a), "l"(w));
    float xl, xh;
    asm("mov.b64 {%0,%1}, %2;" : "=f"(xl), "=f"(xh) : "l"(x));
    float tl = tanh_fast(xl), th = tanh_fast(xh);
    u64 t;
    asm("mov.b64 %0, {%1,%2};" : "=l"(t) : "f"(tl), "f"(th));
    asm("fma.rn.f32x2 %0, %1, %2, %0;" : "+l"(acc) : "l"(t), "l"(v));
}

// ---------------- GEMM body v3: C[M,N] = A[M,K] . B[N,K]^T ----------------
// 32x64 tile, 128 threads, 4m x 4n microtile, f32x2 k-paired accumulation.
__device__ __forceinline__ void gemm_body32(const float* __restrict__ A,
                                            const float* __restrict__ B,
                                            float* __restrict__ C,
                                            int M, int N, int K, int Kc,
                                            int bx, int by, int bz,
                                            int tid, float* As2, float* Bs2) {
    // As2: [8 k2][32 m][2]  (512 floats)   Bs2: [8 k2][64 n][2] (1024 floats)
    int m0 = bx * 32;
    int n0 = by * 64;
    int k0g = bz * Kc;
    int Kend = min(k0g + Kc, K);
    float* Cout = C + (size_t)bz * M * N;

    int amr = tid >> 2, akq = (tid & 3) * 4;    // A: row amr(0..31), k quad
    int bnr = tid >> 1, bkq = (tid & 1) * 8;    // B: row bnr(0..63), k oct
    int gmA = min(m0 + amr, M - 1);
    const float* Ap = A + (size_t)gmA * K + akq;
    const float* Bp = B + (size_t)(n0 + bnr) * K + bkq;

    int tx = tid & 15;             // n pair-quad: n = n0 + tx*4
    int ty = tid >> 4;             // m pair-quad: m = m0 + ty*4

    u64 acc[4][4];
#pragma unroll
    for (int i = 0; i < 4; i++)
#pragma unroll
        for (int j = 0; j < 4; j++) acc[i][j] = 0ull;

    float4 ar;              // 4 A k-values
    float4 br0, br1;        // 8 B k-values
    {
        int kk = k0g;
        if (kk + 16 <= Kend) {
            ar = *(const float4*)(Ap + kk);
            br0 = *(const float4*)(Bp + kk); br1 = *(const float4*)(Bp + kk + 4);
        } else {
            float t[8];
#pragma unroll
            for (int i = 0; i < 4; i++) t[i] = (kk + akq + i < Kend) ? Ap[kk + i] : 0.f;
            ar = make_float4(t[0], t[1], t[2], t[3]);
#pragma unroll
            for (int i = 0; i < 8; i++) t[i] = (kk + bkq + i < Kend) ? Bp[kk + i] : 0.f;
            br0 = make_float4(t[0], t[1], t[2], t[3]); br1 = make_float4(t[4], t[5], t[6], t[7]);
        }
    }

    for (int k0 = k0g; k0 < Kend; k0 += 16) {
        int ak2 = akq >> 1;        // 0,2,4,6
        *(float2*)&As2[(ak2 + 0) * 64 + amr * 2] = make_float2(ar.x, ar.y);
        *(float2*)&As2[(ak2 + 1) * 64 + amr * 2] = make_float2(ar.z, ar.w);
        int bk2 = bkq >> 1;        // 0 or 4
        *(float2*)&Bs2[(bk2 + 0) * 128 + bnr * 2] = make_float2(br0.x, br0.y);
        *(float2*)&Bs2[(bk2 + 1) * 128 + bnr * 2] = make_float2(br0.z, br0.w);
        *(float2*)&Bs2[(bk2 + 2) * 128 + bnr * 2] = make_float2(br1.x, br1.y);
        *(float2*)&Bs2[(bk2 + 3) * 128 + bnr * 2] = make_float2(br1.z, br1.w);
        __syncthreads();

        float4 nar, nbr0, nbr1;
        int kn = k0 + 16;
        bool more = kn < Kend;
        if (more) {
            if (kn + 16 <= Kend) {
                nar = *(const float4*)(Ap + kn);
                nbr0 = *(const float4*)(Bp + kn); nbr1 = *(const float4*)(Bp + kn + 4);
            } else {
                float t[8];
#pragma unroll
                for (int i = 0; i < 4; i++) t[i] = (kn + akq + i < Kend) ? Ap[kn + i] : 0.f;
                nar = make_float4(t[0], t[1], t[2], t[3]);
#pragma unroll
                for (int i = 0; i < 8; i++) t[i] = (kn + bkq + i < Kend) ? Bp[kn + i] : 0.f;
                nbr0 = make_float4(t[0], t[1], t[2], t[3]); nbr1 = make_float4(t[4], t[5], t[6], t[7]);
            }
        }

#pragma unroll
        for (int k2 = 0; k2 < 8; k2++) {
            ulonglong2 A01 = *(const ulonglong2*)&As2[k2 * 64 + ty * 8];
            ulonglong2 A23 = *(const ulonglong2*)&As2[k2 * 64 + ty * 8 + 4];
            ulonglong2 B01 = *(const ulonglong2*)&Bs2[k2 * 128 + tx * 8];
            ulonglong2 B23 = *(const ulonglong2*)&Bs2[k2 * 128 + tx * 8 + 4];
            u64 am[4] = {A01.x, A01.y, A23.x, A23.y};
            u64 bn[4] = {B01.x, B01.y, B23.x, B23.y};
#pragma unroll
            for (int i = 0; i < 4; i++) {
                fma2(acc[i][0], am[i], bn[0]);
                fma2(acc[i][1], am[i], bn[1]);
                fma2(acc[i][2], am[i], bn[2]);
                fma2(acc[i][3], am[i], bn[3]);
            }
        }
        __syncthreads();
        if (more) { ar = nar; br0 = nbr0; br1 = nbr1; }
    }

#pragma unroll
    for (int i = 0; i < 4; i++) {
        int gm = m0 + ty * 4 + i;
        if (gm >= M) continue;
        float4 o;
        o.x = unpk_sum(acc[i][0]);
        o.y = unpk_sum(acc[i][1]);
        o.z = unpk_sum(acc[i][2]);
        o.w = unpk_sum(acc[i][3]);
        *(float4*)&Cout[(size_t)gm * N + n0 + tx * 4] = o;
    }
}

// ---------------- K1 fat kernel: fc_1 gemm + fc_2 gemm + veff prep ----------------
// blocks [0,256): fc_1 split-K-2 gemm; [256,528): fc_2 gemm; [528,656): veff partials.
__global__ void __launch_bounds__(128) fat_kernel(const float* __restrict__ audio,
                                                  const float* __restrict__ word,
                                                  const float* __restrict__ W1,
                                                  const float* __restrict__ W2,
                                                  const float* __restrict__ W3,
                                                  const float* __restrict__ Wa) {
    __shared__ __align__(16) float As2[8 * 64];
    __shared__ __align__(16) float Bs2[8 * 128];
    __shared__ float red[4][33];
    int ib = blockIdx.x;
    int tid = threadIdx.x;
    if (ib < 256) {
        // K2: a partials = audio @ W1^T, split-K 2
        int r = ib & 127;
        gemm_body32(audio, W1, (float*)&g_apart[0], BT_, H_, DA_, DA_ / 2,
                    r & 7, r >> 3, ib >> 7, tid, As2, Bs2);
    } else if (ib < 528) {
        int j = ib - 256;   // 0..271 -> (x 0..16, y 0..15)
        gemm_body32(word, W2, (float*)&g_w[0], C_, H_, DW_, DW_,
                    j % 17, j / 17, 0, tid, As2, Bs2);
    } else {
        // veff partials: p = 0..127; hb = p&31 (32 h), ob = p>>5 (256 o rows)
        int p = ib - 528;
        int hb = p & 31, ob = p >> 5;
        int hl = tid & 31;
        int og = tid >> 5;          // 0..3
        int h = hb * 32 + hl;
        float acc = 0.f;
#pragma unroll 8
        for (int o = ob * 256 + og; o < ob * 256 + 256; o += 4)
            acc += Wa[o] * W3[(size_t)o * H_ + h];
        red[og][hl] = acc;
        __syncthreads();
        if (og == 0)
            g_vpart[ob * H_ + h] = red[0][hl] + red[1][hl] + red[2][hl] + red[3][hl];
    }
}

// ---------------- K4: partial score over one H half, f32x2 packed ----------------
// CTA tile 16 bt x 64 c, 256 threads, 2bt x 2c per thread. grid (16, 9, 2).
__global__ void __launch_bounds__(256, 2) score_kernel() {
    __shared__ __align__(16) float a_s[16][64];
    __shared__ __align__(16) float w_s[64][68];
    __shared__ __align__(16) float v_s[64];
    int tid  = threadIdx.x;
    int lane = tid & 31;
    int warp = tid >> 5;            // 0..7
    int bt0  = blockIdx.x * 16;
    int c0   = blockIdx.y * 64;
    int hb0  = blockIdx.z * (H_ / 2);
    float* out = blockIdx.z ? g_score1 : g_score0;
    u64 p00 = 0ull, p01 = 0ull, p10 = 0ull, p11 = 0ull;

    for (int h0 = hb0; h0 < hb0 + H_ / 2; h0 += 64) {
        // a tile with fused split-K merge
        {
            int r = tid >> 4;              // 0..15
            int c4 = (tid & 15) * 4;       // 0..60
            size_t ai = (size_t)(bt0 + r) * H_ + h0 + c4;
            float4 x = *(const float4*)&g_apart[ai];
            float4 y = *(const float4*)&g_apart[(size_t)BT_ * H_ + ai];
            x.x += y.x; x.y += y.y; x.z += y.z; x.w += y.w;
            *(float4*)&a_s[r][c4] = x;
        }
        // v tile: sum the 4 o-chunk partials
        if (tid < 64) {
            int h = h0 + tid;
            v_s[tid] = g_vpart[h] + g_vpart[H_ + h] + g_vpart[2 * H_ + h] + g_vpart[3 * H_ + h];
        }
        // w tile, c-major
        {
            int c = tid >> 2, q = tid & 3;
            int cg = c0 + c;
            bool ok = cg < C_;
            const float4* wrow = (const float4*)(g_w + (size_t)(ok ? cg : C_ - 1) * H_ + h0);
            float4 z = make_float4(0.f, 0.f, 0.f, 0.f);
#pragma unroll
            for (int i = 0; i < 4; i++)
                *(float4*)&w_s[c][q * 16 + i * 4] = ok ? wrow[q * 4 + i] : z;
        }
        __syncthreads();

#pragma unroll
        for (int hh = 0; hh < 16; hh++) {
            ulonglong2 av0 = *(const ulonglong2*)&a_s[warp][hh * 4];
            ulonglong2 av1 = *(const ulonglong2*)&a_s[warp + 8][hh * 4];
            ulonglong2 wA  = *(const ulonglong2*)&w_s[lane][hh * 4];
            ulonglong2 wB  = *(const ulonglong2*)&w_s[lane + 32][hh * 4];
            ulonglong2 vv  = *(const ulonglong2*)&v_s[hh * 4];
            tvstep(p00, av0.x, wA.x, vv.x);
            tvstep(p01, av0.x, wB.x, vv.x);
            tvstep(p10, av1.x, wA.x, vv.x);
            tvstep(p11, av1.x, wB.x, vv.x);
            tvstep(p00, av0.y, wA.y, vv.y);
            tvstep(p01, av0.y, wB.y, vv.y);
            tvstep(p10, av1.y, wA.y, vv.y);
            tvstep(p11, av1.y, wB.y, vv.y);
        }
        __syncthreads();
    }
    float s00 = unpk_sum(p00), s01 = unpk_sum(p01);
    float s10 = unpk_sum(p10), s11 = unpk_sum(p11);
    int ca = c0 + lane, cb = c0 + lane + 32;
    int base0 = (bt0 + warp) * C_;
    int base1 = (bt0 + warp + 8) * C_;
    if (ca < C_) {
        out[base0 + ca] = s00;
        out[base1 + ca] = s10;
    }
    if (cb < C_) {
        out[base0 + cb] = s01;
        out[base1 + cb] = s11;
    }
}

// ---------------- K5: softmax over T per (b,c), coalesced ----------------
__global__ void softmax_kernel() {
    __shared__ float redm[8][33], reds[8][33];
    int cl = threadIdx.x & 31;
    int tg = threadIdx.x >> 5;     // 0..7
    int b  = blockIdx.y;
    int c  = blockIdx.x * 32 + cl;
    bool ok = c < C_;
    int cc = ok ? c : C_ - 1;

    float v[16];
    float m = -1e30f;
#pragma unroll
    for (int i = 0; i < 16; i++) {
        int idx = (b * T_ + tg + i * 8) * C_ + cc;
        v[i] = g_score0[idx] + g_score1[idx];
        m = fmaxf(m, v[i]);
    }
    redm[tg][cl] = m;
    __syncthreads();
    m = redm[0][cl];
#pragma unroll
    for (int g = 1; g < 8; g++) m = fmaxf(m, redm[g][cl]);

    float s = 0.f;
#pragma unroll
    for (int i = 0; i < 16; i++) {
        v[i] = __expf(v[i] - m);
        s += v[i];
    }
    reds[tg][cl] = s;
    __syncthreads();
    s = reds[0][cl];
#pragma unroll
    for (int g = 1; g < 8; g++) s += reds[g][cl];
    float inv = 1.f / s;
    if (ok) {
#pragma unroll
        for (int i = 0; i < 16; i++)
            g_coef[(b * T_ + tg + i * 8) * C_ + c] = v[i] * inv;
    }
}

// ---------------- K6: out[b,c,d] = sum_t coef[b,t,c] * audio[b,t,d] ----------------
// TN form, 32x64 tile, 128 threads, 4x4 micro, f32x2. grid (17, 16, 2).
__global__ void __launch_bounds__(128) pool3(const float* __restrict__ audio,
                                             float* __restrict__ out) {
    __shared__ __align__(16) float As2[8 * 64];    // [k2][c][2]
    __shared__ __align__(16) float Bs2[8 * 128];   // [k2][d][2]
    int b = blockIdx.z;
    const float* coefb = g_coef + (size_t)b * T_ * C_;
    const float* audb  = audio + (size_t)b * T_ * DA_;
    float* Cout = out + (size_t)b * C_ * DA_;
    int tid = threadIdx.x;
    int m0 = blockIdx.x * 32;
    int n0 = blockIdx.y * 64;

    int ac  = tid & 31;            // c lane
    int atg = tid >> 5;            // 0..3 t-group (4 t each)
    int gmc = min(m0 + ac, C_ - 1);
    int bd  = tid & 63;            // d lane
    int btg = tid >> 6;            // 0..1 t-group (8 t each)

    int tx = tid & 15, ty = tid >> 4;

    u64 acc[4][4];
#pragma unroll
    for (int i = 0; i < 4; i++)
#pragma unroll
        for (int j = 0; j < 4; j++) acc[i][j] = 0ull;

    float pa[4], pb[8];
#pragma unroll
    for (int i = 0; i < 4; i++)
        pa[i] = coefb[(size_t)(atg * 4 + i) * C_ + gmc];
#pragma unroll
    for (int i = 0; i < 8; i++)
        pb[i] = audb[(size_t)(btg * 8 + i) * DA_ + n0 + bd];

    for (int k0 = 0; k0 < T_; k0 += 16) {
        *(float2*)&As2[(atg * 2 + 0) * 64 + ac * 2] = make_float2(pa[0], pa[1]);
        *(float2*)&As2[(atg * 2 + 1) * 64 + ac * 2] = make_float2(pa[2], pa[3]);
#pragma unroll
        for (int i = 0; i < 4; i++)
            *(float2*)&Bs2[(btg * 4 + i) * 128 + bd * 2] = make_float2(pb[2 * i], pb[2 * i + 1]);
        __syncthreads();
        int kn = k0 + 16;
        if (kn < T_) {
#pragma unroll
            for (int i = 0; i < 4; i++)
                pa[i] = coefb[(size_t)(kn + atg * 4 + i) * C_ + gmc];
#pragma unroll
            for (int i = 0; i < 8; i++)
                pb[i] = audb[(size_t)(kn + btg * 8 + i) * DA_ + n0 + bd];
        }
#pragma unroll
        for (int k2 = 0; k2 < 8; k2++) {
            ulonglong2 A01 = *(const ulonglong2*)&As2[k2 * 64 + ty * 8];
            ulonglong2 A23 = *(const ulonglong2*)&As2[k2 * 64 + ty * 8 + 4];
            ulonglong2 B01 = *(const ulonglong2*)&Bs2[k2 * 128 + tx * 8];
            ulonglong2 B23 = *(const ulonglong2*)&Bs2[k2 * 128 + tx * 8 + 4];
            u64 am[4] = {A01.x, A01.y, A23.x, A23.y};
            u64 bn[4] = {B01.x, B01.y, B23.x, B23.y};
#pragma unroll
            for (int i = 0; i < 4; i++) {
                fma2(acc[i][0], am[i], bn[0]);
                fma2(acc[i][1], am[i], bn[1]);
                fma2(acc[i][2], am[i], bn[2]);
                fma2(acc[i][3], am[i], bn[3]);
            }
        }
        __syncthreads();
    }

#pragma unroll
    for (int i = 0; i < 4; i++) {
        int gm2 = m0 + ty * 4 + i;
        if (gm2 >= C_) continue;
        float4 o;
        o.x = unpk_sum(acc[i][0]);
        o.y = unpk_sum(acc[i][1]);
        o.z = unpk_sum(acc[i][2]);
        o.w = unpk_sum(acc[i][3]);
        *(float4*)&Cout[(size_t)gm2 * DA_ + n0 + tx * 4] = o;
    }
}

// ---------------- launch ----------------
extern "C" void kernel_launch(void* const* d_in, const int* in_sizes, int n_in,
                              void* d_out, int out_size) {
    const float* audio = (const float*)d_in[0];   // [B,T,DA]
    const float* word  = (const float*)d_in[1];   // [C,DW]
    const float* W1    = (const float*)d_in[2];   // [H,DA]
    const float* W2    = (const float*)d_in[3];   // [H,DW]
    const float* W3    = (const float*)d_in[4];   // [H,H]
    const float* Wa    = (const float*)d_in[6];   // [1,H]
    float* out = (float*)d_out;                   // [B,C,DA]
    (void)in_sizes; (void)n_in; (void)out_size;

    // (1) fused: fc_1 gemm (split-K 2) + fc_2 gemm + veff prep, 32x64 tiles
    fat_kernel<<<656, 128>>>(audio, word, W1, W2, W3, Wa);
    // (2) fused tanh-dot score, f32x2 packed
    score_kernel<<<dim3(BT_ / 16, (C_ + 63) / 64, 2), 256>>>();
    // (3) softmax over T, coalesced
    softmax_kernel<<<dim3((C_ + 31) / 32, B_), 256>>>();
    // (4) softmax-weighted pooling, 32x64 tiles
    pool3<<<dim3((C_ + 31) / 32, DA_ / 64, B_), 128>>>(audio, out);
}

// round 8
// speedup vs baseline: 1.2130x; 1.2130x over previous
#include <cuda_runtime.h>
#include <cuda_bf16.h>

// Problem constants
#define B_   2
#define T_   128
#define C_   527
#define DA_  1024
#define DW_  300
#define H_   1024
#define BT_  (B_ * T_)   // 256

typedef unsigned long long u64;

// ---------------- device scratch ----------------
__device__ float g_apart[4 * BT_ * H_];  // split-K-4 partials for fc_1
__device__ float g_w[C_ * H_];           // fc_2 output [527,1024]
__device__ float g_vpart[4 * H_];        // veff partials (4 o-chunks)
__device__ float g_score0[BT_ * C_];     // partial score (h first half)
__device__ float g_score1[BT_ * C_];     // partial score (h second half)
__device__ float g_coef[BT_ * C_];       // softmax over T

__device__ __forceinline__ float tanh_fast(float x) {
    float y;
    asm("tanh.approx.f32 %0, %1;" : "=f"(y) : "f"(x));
    return y;
}
__device__ __forceinline__ void fma2(u64& d, u64 a, u64 b) {
    asm("fma.rn.f32x2 %0, %1, %2, %0;" : "+l"(d) : "l"(a), "l"(b));
}
__device__ __forceinline__ float unpk_sum(u64 v) {
    float lo, hi;
    asm("mov.b64 {%0,%1}, %2;" : "=f"(lo), "=f"(hi) : "l"(v));
    return lo + hi;
}
// acc += tanh(a*w) * v, packed over an h-pair
__device__ __forceinline__ void tvstep(u64& acc, u64 a, u64 w, u64 v) {
    u64 x;
    asm("mul.rn.f32x2 %0, %1, %2;" : "=l"(x) : "l"(a), "l"(w));
    float xl, xh;
    asm("mov.b64 {%0,%1}, %2;" : "=f"(xl), "=f"(xh) : "l"(x));
    float tl = tanh_fast(xl), th = tanh_fast(xh);
    u64 t;
    asm("mov.b64 %0, {%1,%2};" : "=l"(t) : "f"(tl), "f"(th));
    asm("fma.rn.f32x2 %0, %1, %2, %0;" : "+l"(acc) : "l"(t), "l"(v));
}

// ---------------- GEMM body: C[M,N] = A[M,K] . B[N,K]^T ----------------
// 64x64 tile, 128 threads, 8m x 4n microtile, f32x2 k-paired accumulation.
__device__ __forceinline__ void gemm_body(const float* __restrict__ A,
                                          const float* __restrict__ B,
                                          float* __restrict__ C,
                                          int M, int N, int K, int Kc,
                                          int bx, int by, int bz,
                                          int tid, float* As2, float* Bs2) {
    int m0 = bx * 64;
    int n0 = by * 64;
    int k0g = bz * Kc;
    int Kend = min(k0g + Kc, K);
    float* Cout = C + (size_t)bz * M * N;

    int lr = tid >> 1;
    int lk = (tid & 1) * 8;
    int k2b = lk >> 1;
    int gmA = min(m0 + lr, M - 1);
    const float* Ap = A + (size_t)gmA * K + lk;
    const float* Bp = B + (size_t)(n0 + lr) * K + lk;

    int tx = tid & 15;
    int ty = tid >> 4;

    u64 acc[8][4];
#pragma unroll
    for (int i = 0; i < 8; i++)
#pragma unroll
        for (int j = 0; j < 4; j++) acc[i][j] = 0ull;

    float4 a0, a1, b0, b1;
    {
        int kk = k0g;
        if (kk + 16 <= Kend) {
            a0 = *(const float4*)(Ap + kk); a1 = *(const float4*)(Ap + kk + 4);
            b0 = *(const float4*)(Bp + kk); b1 = *(const float4*)(Bp + kk + 4);
        } else {
            float t[8];
#pragma unroll
            for (int i = 0; i < 8; i++) t[i] = (kk + lk + i < Kend) ? Ap[kk + i] : 0.f;
            a0 = make_float4(t[0], t[1], t[2], t[3]); a1 = make_float4(t[4], t[5], t[6], t[7]);
#pragma unroll
            for (int i = 0; i < 8; i++) t[i] = (kk + lk + i < Kend) ? Bp[kk + i] : 0.f;
            b0 = make_float4(t[0], t[1], t[2], t[3]); b1 = make_float4(t[4], t[5], t[6], t[7]);
        }
    }

    for (int k0 = k0g; k0 < Kend; k0 += 16) {
        *(float2*)&As2[(k2b + 0) * 128 + lr * 2] = make_float2(a0.x, a0.y);
        *(float2*)&As2[(k2b + 1) * 128 + lr * 2] = make_float2(a0.z, a0.w);
        *(float2*)&As2[(k2b + 2) * 128 + lr * 2] = make_float2(a1.x, a1.y);
        *(float2*)&As2[(k2b + 3) * 128 + lr * 2] = make_float2(a1.z, a1.w);
        *(float2*)&Bs2[(k2b + 0) * 128 + lr * 2] = make_float2(b0.x, b0.y);
        *(float2*)&Bs2[(k2b + 1) * 128 + lr * 2] = make_float2(b0.z, b0.w);
        *(float2*)&Bs2[(k2b + 2) * 128 + lr * 2] = make_float2(b1.x, b1.y);
        *(float2*)&Bs2[(k2b + 3) * 128 + lr * 2] = make_float2(b1.z, b1.w);
        __syncthreads();

        float4 na0, na1, nb0, nb1;
        int kn = k0 + 16;
        bool more = kn < Kend;
        if (more) {
            if (kn + 16 <= Kend) {
                na0 = *(const float4*)(Ap + kn); na1 = *(const float4*)(Ap + kn + 4);
                nb0 = *(const float4*)(Bp + kn); nb1 = *(const float4*)(Bp + kn + 4);
            } else {
                float t[8];
#pragma unroll
                for (int i = 0; i < 8; i++) t[i] = (kn + lk + i < Kend) ? Ap[kn + i] : 0.f;
                na0 = make_float4(t[0], t[1], t[2], t[3]); na1 = make_float4(t[4], t[5], t[6], t[7]);
#pragma unroll
                for (int i = 0; i < 8; i++) t[i] = (kn + lk + i < Kend) ? Bp[kn + i] : 0.f;
                nb0 = make_float4(t[0], t[1], t[2], t[3]); nb1 = make_float4(t[4], t[5], t[6], t[7]);
            }
        }

#pragma unroll
        for (int k2 = 0; k2 < 8; k2++) {
            ulonglong2 A01 = *(const ulonglong2*)&As2[k2 * 128 + ty * 16];
            ulonglong2 A23 = *(const ulonglong2*)&As2[k2 * 128 + ty * 16 + 4];
            ulonglong2 A45 = *(const ulonglong2*)&As2[k2 * 128 + ty * 16 + 8];
            ulonglong2 A67 = *(const ulonglong2*)&As2[k2 * 128 + ty * 16 + 12];
            ulonglong2 B01 = *(const ulonglong2*)&Bs2[k2 * 128 + tx * 8];
            ulonglong2 B23 = *(const ulonglong2*)&Bs2[k2 * 128 + tx * 8 + 4];
            u64 am[8] = {A01.x, A01.y, A23.x, A23.y, A45.x, A45.y, A67.x, A67.y};
            u64 bn[4] = {B01.x, B01.y, B23.x, B23.y};
#pragma unroll
            for (int i = 0; i < 8; i++) {
                fma2(acc[i][0], am[i], bn[0]);
                fma2(acc[i][1], am[i], bn[1]);
                fma2(acc[i][2], am[i], bn[2]);
                fma2(acc[i][3], am[i], bn[3]);
            }
        }
        __syncthreads();
        if (more) { a0 = na0; a1 = na1; b0 = nb0; b1 = nb1; }
    }

#pragma unroll
    for (int i = 0; i < 8; i++) {
        int gm = m0 + ty * 8 + i;
        if (gm >= M) continue;
        float4 o;
        o.x = unpk_sum(acc[i][0]);
        o.y = unpk_sum(acc[i][1]);
        o.z = unpk_sum(acc[i][2]);
        o.w = unpk_sum(acc[i][3]);
        *(float4*)&Cout[(size_t)gm * N + n0 + tx * 4] = o;
    }
}

// ---------------- K1 fat kernel: fc_1 gemm + fc_2 gemm + veff prep ----------------
// blocks [0,256): fc_1 split-K-4 gemm; [256,400): fc_2 gemm; [400,528): veff partials.
__global__ void __launch_bounds__(128) fat_kernel(const float* __restrict__ audio,
                                                  const float* __restrict__ word,
                                                  const float* __restrict__ W1,
                                                  const float* __restrict__ W2,
                                                  const float* __restrict__ W3,
                                                  const float* __restrict__ Wa) {
    __shared__ __align__(16) float As2[8 * 128];
    __shared__ __align__(16) float Bs2[8 * 128];
    __shared__ float red[4][33];
    int ib = blockIdx.x;
    int tid = threadIdx.x;
    if (ib < 256) {
        // fc_1: a partials = audio @ W1^T, split-K 4 (Kc = 256)
        gemm_body(audio, W1, (float*)&g_apart[0], BT_, H_, DA_, DA_ / 4,
                  ib & 3, (ib >> 2) & 15, ib >> 6, tid, As2, Bs2);
    } else if (ib < 400) {
        int j = ib - 256;   // 0..143 -> (x 0..8, y 0..15)
        gemm_body(word, W2, (float*)&g_w[0], C_, H_, DW_, DW_,
                  j % 9, j / 9, 0, tid, As2, Bs2);
    } else {
        // veff partials: p = 0..127; hb = p&31 (32 h), ob = p>>5 (256 o rows)
        int p = ib - 400;
        int hb = p & 31, ob = p >> 5;
        int hl = tid & 31;
        int og = tid >> 5;          // 0..3
        int h = hb * 32 + hl;
        float acc = 0.f;
#pragma unroll 8
        for (int o = ob * 256 + og; o < ob * 256 + 256; o += 4)
            acc += Wa[o] * W3[(size_t)o * H_ + h];
        red[og][hl] = acc;
        __syncthreads();
        if (og == 0)
            g_vpart[ob * H_ + h] = red[0][hl] + red[1][hl] + red[2][hl] + red[3][hl];
    }
}

// ---------------- K4: partial score over one H half, f32x2 packed ----------------
// CTA tile 16 bt x 64 c, 256 threads, 2bt x 2c per thread. grid (16, 9, 2).
__global__ void __launch_bounds__(256, 2) score_kernel() {
    __shared__ __align__(16) float a_s[16][64];
    __shared__ __align__(16) float w_s[64][68];
    __shared__ __align__(16) float v_s[64];
    int tid  = threadIdx.x;
    int lane = tid & 31;
    int warp = tid >> 5;            // 0..7
    int bt0  = blockIdx.x * 16;
    int c0   = blockIdx.y * 64;
    int hb0  = blockIdx.z * (H_ / 2);
    float* out = blockIdx.z ? g_score1 : g_score0;
    u64 p00 = 0ull, p01 = 0ull, p10 = 0ull, p11 = 0ull;

    for (int h0 = hb0; h0 < hb0 + H_ / 2; h0 += 64) {
        // a tile with fused split-K-4 merge
        {
            int r = tid >> 4;              // 0..15
            int c4 = (tid & 15) * 4;       // 0..60
            size_t ai = (size_t)(bt0 + r) * H_ + h0 + c4;
            const size_t S = (size_t)BT_ * H_;
            float4 x = *(const float4*)&g_apart[ai];
            float4 y = *(const float4*)&g_apart[S + ai];
            float4 z = *(const float4*)&g_apart[2 * S + ai];
            float4 w = *(const float4*)&g_apart[3 * S + ai];
            x.x = (x.x + y.x) + (z.x + w.x);
            x.y = (x.y + y.y) + (z.y + w.y);
            x.z = (x.z + y.z) + (z.z + w.z);
            x.w = (x.w + y.w) + (z.w + w.w);
            *(float4*)&a_s[r][c4] = x;
        }
        // v tile: sum the 4 o-chunk partials
        if (tid < 64) {
            int h = h0 + tid;
            v_s[tid] = g_vpart[h] + g_vpart[H_ + h] + g_vpart[2 * H_ + h] + g_vpart[3 * H_ + h];
        }
        // w tile, c-major
        {
            int c = tid >> 2, q = tid & 3;
            int cg = c0 + c;
            bool ok = cg < C_;
            const float4* wrow = (const float4*)(g_w + (size_t)(ok ? cg : C_ - 1) * H_ + h0);
            float4 z = make_float4(0.f, 0.f, 0.f, 0.f);
#pragma unroll
            for (int i = 0; i < 4; i++)
                *(float4*)&w_s[c][q * 16 + i * 4] = ok ? wrow[q * 4 + i] : z;
        }
        __syncthreads();

#pragma unroll
        for (int hh = 0; hh < 16; hh++) {
            ulonglong2 av0 = *(const ulonglong2*)&a_s[warp][hh * 4];
            ulonglong2 av1 = *(const ulonglong2*)&a_s[warp + 8][hh * 4];
            ulonglong2 wA  = *(const ulonglong2*)&w_s[lane][hh * 4];
            ulonglong2 wB  = *(const ulonglong2*)&w_s[lane + 32][hh * 4];
            ulonglong2 vv  = *(const ulonglong2*)&v_s[hh * 4];
            tvstep(p00, av0.x, wA.x, vv.x);
            tvstep(p01, av0.x, wB.x, vv.x);
            tvstep(p10, av1.x, wA.x, vv.x);
            tvstep(p11, av1.x, wB.x, vv.x);
            tvstep(p00, av0.y, wA.y, vv.y);
            tvstep(p01, av0.y, wB.y, vv.y);
            tvstep(p10, av1.y, wA.y, vv.y);
            tvstep(p11, av1.y, wB.y, vv.y);
        }
        __syncthreads();
    }
    float s00 = unpk_sum(p00), s01 = unpk_sum(p01);
    float s10 = unpk_sum(p10), s11 = unpk_sum(p11);
    int ca = c0 + lane, cb = c0 + lane + 32;
    int base0 = (bt0 + warp) * C_;
    int base1 = (bt0 + warp + 8) * C_;
    if (ca < C_) {
        out[base0 + ca] = s00;
        out[base1 + ca] = s10;
    }
    if (cb < C_) {
        out[base0 + cb] = s01;
        out[base1 + cb] = s11;
    }
}

// ---------------- K5: softmax over T per (b,c), coalesced ----------------
__global__ void softmax_kernel() {
    __shared__ float redm[8][33], reds[8][33];
    int cl = threadIdx.x & 31;
    int tg = threadIdx.x >> 5;     // 0..7
    int b  = blockIdx.y;
    int c  = blockIdx.x * 32 + cl;
    bool ok = c < C_;
    int cc = ok ? c : C_ - 1;

    float v[16];
    float m = -1e30f;
#pragma unroll
    for (int i = 0; i < 16; i++) {
        int idx = (b * T_ + tg + i * 8) * C_ + cc;
        v[i] = g_score0[idx] + g_score1[idx];
        m = fmaxf(m, v[i]);
    }
    redm[tg][cl] = m;
    __syncthreads();
    m = redm[0][cl];
#pragma unroll
    for (int g = 1; g < 8; g++) m = fmaxf(m, redm[g][cl]);

    float s = 0.f;
#pragma unroll
    for (int i = 0; i < 16; i++) {
        v[i] = __expf(v[i] - m);
        s += v[i];
    }
    reds[tg][cl] = s;
    __syncthreads();
    s = reds[0][cl];
#pragma unroll
    for (int g = 1; g < 8; g++) s += reds[g][cl];
    float inv = 1.f / s;
    if (ok) {
#pragma unroll
        for (int i = 0; i < 16; i++)
            g_coef[(b * T_ + tg + i * 8) * C_ + c] = v[i] * inv;
    }
}

// ---------------- K6: out[b,c,d] = sum_t coef[b,t,c] * audio[b,t,d] ----------------
// TN form: both operands K-major. 64x64 tile, 128 threads, 8x4 micro, f32x2.
__global__ void __launch_bounds__(128) pool2(const float* __restrict__ audio,
                                             float* __restrict__ out) {
    __shared__ __align__(16) float As2[8 * 128];   // [k2][c][2]
    __shared__ __align__(16) float Bs2[8 * 128];   // [k2][d][2]
    int b = blockIdx.z;
    const float* coefb = g_coef + (size_t)b * T_ * C_;
    const float* audb  = audio + (size_t)b * T_ * DA_;
    float* Cout = out + (size_t)b * C_ * DA_;
    int tid = threadIdx.x;
    int m0 = blockIdx.x * 64;
    int n0 = blockIdx.y * 64;

    int lm  = tid & 63;
    int lkg = tid >> 6;
    int gm  = min(m0 + lm, C_ - 1);

    int tx = tid & 15, ty = tid >> 4;

    u64 acc[8][4];
#pragma unroll
    for (int i = 0; i < 8; i++)
#pragma unroll
        for (int j = 0; j < 4; j++) acc[i][j] = 0ull;

    float2 pa[4], pb[4];
#pragma unroll
    for (int i = 0; i < 4; i++) {
        int ke = lkg * 8 + 2 * i;
        pa[i] = make_float2(coefb[(size_t)ke * C_ + gm], coefb[(size_t)(ke + 1) * C_ + gm]);
        pb[i] = make_float2(audb[(size_t)ke * DA_ + n0 + lm], audb[(size_t)(ke + 1) * DA_ + n0 + lm]);
    }

    for (int k0 = 0; k0 < T_; k0 += 16) {
#pragma unroll
        for (int i = 0; i < 4; i++) {
            *(float2*)&As2[(lkg * 4 + i) * 128 + lm * 2] = pa[i];
            *(float2*)&Bs2[(lkg * 4 + i) * 128 + lm * 2] = pb[i];
        }
        __syncthreads();
        int kn = k0 + 16;
        if (kn < T_) {
#pragma unroll
            for (int i = 0; i < 4; i++) {
                int ke = kn + lkg * 8 + 2 * i;
                pa[i] = make_float2(coefb[(size_t)ke * C_ + gm], coefb[(size_t)(ke + 1) * C_ + gm]);
                pb[i] = make_float2(audb[(size_t)ke * DA_ + n0 + lm], audb[(size_t)(ke + 1) * DA_ + n0 + lm]);
            }
        }
#pragma unroll
        for (int k2 = 0; k2 < 8; k2++) {
            ulonglong2 A01 = *(const ulonglong2*)&As2[k2 * 128 + ty * 16];
            ulonglong2 A23 = *(const ulonglong2*)&As2[k2 * 128 + ty * 16 + 4];
            ulonglong2 A45 = *(const ulonglong2*)&As2[k2 * 128 + ty * 16 + 8];
            ulonglong2 A67 = *(const ulonglong2*)&As2[k2 * 128 + ty * 16 + 12];
            ulonglong2 B01 = *(const ulonglong2*)&Bs2[k2 * 128 + tx * 8];
            ulonglong2 B23 = *(const ulonglong2*)&Bs2[k2 * 128 + tx * 8 + 4];
            u64 am[8] = {A01.x, A01.y, A23.x, A23.y, A45.x, A45.y, A67.x, A67.y};
            u64 bn[4] = {B01.x, B01.y, B23.x, B23.y};
#pragma unroll
            for (int i = 0; i < 8; i++) {
                fma2(acc[i][0], am[i], bn[0]);
                fma2(acc[i][1], am[i], bn[1]);
                fma2(acc[i][2], am[i], bn[2]);
                fma2(acc[i][3], am[i], bn[3]);
            }
        }
        __syncthreads();
    }

#pragma unroll
    for (int i = 0; i < 8; i++) {
        int gm2 = m0 + ty * 8 + i;
        if (gm2 >= C_) continue;
        float4 o;
        o.x = unpk_sum(acc[i][0]);
        o.y = unpk_sum(acc[i][1]);
        o.z = unpk_sum(acc[i][2]);
        o.w = unpk_sum(acc[i][3]);
        *(float4*)&Cout[(size_t)gm2 * DA_ + n0 + tx * 4] = o;
    }
}

// ---------------- launch ----------------
extern "C" void kernel_launch(void* const* d_in, const int* in_sizes, int n_in,
                              void* d_out, int out_size) {
    const float* audio = (const float*)d_in[0];   // [B,T,DA]
    const float* word  = (const float*)d_in[1];   // [C,DW]
    const float* W1    = (const float*)d_in[2];   // [H,DA]
    const float* W2    = (const float*)d_in[3];   // [H,DW]
    const float* W3    = (const float*)d_in[4];   // [H,H]
    const float* Wa    = (const float*)d_in[6];   // [1,H]
    float* out = (float*)d_out;                   // [B,C,DA]
    (void)in_sizes; (void)n_in; (void)out_size;

    // (1) fused: fc_1 gemm (split-K 4) + fc_2 gemm + veff prep, 64x64 tiles
    fat_kernel<<<528, 128>>>(audio, word, W1, W2, W3, Wa);
    // (2) fused tanh-dot score, f32x2 packed
    score_kernel<<<dim3(BT_ / 16, (C_ + 63) / 64, 2), 256>>>();
    // (3) softmax over T, coalesced
    softmax_kernel<<<dim3((C_ + 31) / 32, B_), 256>>>();
    // (4) softmax-weighted pooling, 64x64 tiles
    pool2<<<dim3((C_ + 63) / 64, DA_ / 64, B_), 128>>>(audio, out);
}